// round 4
// baseline (speedup 1.0000x reference)
#include <cuda_runtime.h>
#include <math_constants.h>

// Prefix-max (cumulative max) along H for x of shape (B=32, C=1, H=1024, W=1024), fp32.
// Layout: x[(b*H + h)*W + w]. 32768 independent columns (b,w), scan length H=1024.
//
// Tile: 256-thread block owns 8 consecutive float-columns x full H.
//   __launch_bounds__(256, 5): ~5 CTAs/SM -> fine-grained phase interleaving,
//   keeping DRAM fed while other CTAs are in their scan/barrier phase.
//   thread t: c = t & 7, chunk = t >> 3 (32 chunks of 32 rows).
//   Phase 1: 32 coalesced scalar loads -> registers, local prefix-max.
//   Phase 2: chunk totals -> smem (1 barrier); warp k shuffle-scans column k
//            (5 shfl rounds, register-resident); write back (1 barrier).
//   Phase 3: apply exclusive carry, 32 coalesced stores.

#define H_DIM 1024
#define W_DIM 1024
#define COLS_PER_BLOCK 8
#define CHUNKS 32
#define ROWS_PER_THREAD 32   // H_DIM / CHUNKS

__global__ __launch_bounds__(256, 5)
void cummax_kernel(const float* __restrict__ x, float* __restrict__ out) {
    const int tid   = threadIdx.x;
    const int c     = tid & (COLS_PER_BLOCK - 1);   // 0..7
    const int chunk = tid >> 3;                     // 0..31
    const int wid   = tid >> 5;                     // 0..7
    const int lane  = tid & 31;

    const int col = blockIdx.x * COLS_PER_BLOCK + c;  // 0..32767 (1024 % 8 == 0: no b straddle)
    const int b   = col >> 10;
    const int w   = col & (W_DIM - 1);

    const int base = b * (H_DIM * W_DIM) + w + chunk * ROWS_PER_THREAD * W_DIM;
    const float* __restrict__ src = x   + base;
    float* __restrict__ dst       = out + base;

    // Phase 1: load 32 rows (coalesced: warp covers 4 rows x 32B fully-used sectors).
    float v[ROWS_PER_THREAD];
#pragma unroll
    for (int i = 0; i < ROWS_PER_THREAD; i++) {
        v[i] = src[i * W_DIM];
    }
#pragma unroll
    for (int i = 1; i < ROWS_PER_THREAD; i++) {
        v[i] = fmaxf(v[i], v[i - 1]);
    }

    // Phase 2: cross-chunk inclusive max-scan of totals via warp shuffles.
    __shared__ float s[CHUNKS][COLS_PER_BLOCK + 1];   // pad -> conflict-free transposed access
    s[chunk][c] = v[ROWS_PER_THREAD - 1];
    __syncthreads();

    // Warp `wid` scans column `wid`: lane = chunk index. 8 warps, 8 columns.
    {
        float t = s[lane][wid];
#pragma unroll
        for (int d = 1; d < 32; d <<= 1) {
            float o = __shfl_up_sync(0xFFFFFFFFu, t, d);
            if (lane >= d) t = fmaxf(t, o);
        }
        s[lane][wid] = t;
    }
    __syncthreads();

    // Phase 3: exclusive carry, apply, store.
    const float carry = (chunk > 0) ? s[chunk - 1][c] : -CUDART_INF_F;
#pragma unroll
    for (int i = 0; i < ROWS_PER_THREAD; i++) {
        dst[i * W_DIM] = fmaxf(v[i], carry);
    }
}

extern "C" void kernel_launch(void* const* d_in, const int* in_sizes, int n_in,
                              void* d_out, int out_size) {
    const float* x = (const float*)d_in[0];
    float* out = (float*)d_out;

    const int total_cols = 32 * W_DIM;                        // 32768
    const int grid = total_cols / COLS_PER_BLOCK;             // 4096
    cummax_kernel<<<grid, 256>>>(x, out);
}

// round 5
// speedup vs baseline: 1.1377x; 1.1377x over previous
#include <cuda_runtime.h>
#include <math_constants.h>

// Prefix-max (cumulative max) along H for x of shape (B=32, C=1, H=1024, W=1024), fp32.
// Layout: x[(b*H + h)*W + w]. 32768 independent columns (b,w), scan length H=1024.
//
// Tile: 512-thread block owns 16 consecutive float-columns x full H,
// processed as TWO halves of 512 rows (16 rows/thread each) to cut register
// pressure (v[16]) and enable 3 CTAs/SM (__launch_bounds__(512,3), 48 warps).
//   thread t: c = t & 15, chunk = t >> 4 (32 chunks of 16 rows per half).
//   Per half: coalesced loads (64B warp segments, proven best in R3/R4),
//   local prefix-max, chunk totals -> smem (1 barrier), warp-per-column
//   shuffle scan (5 shfl rounds, no barrier), read-back (1 barrier),
//   apply carry (incl. cross-half carry), coalesced stores.
// Double-buffered smem: no extra barrier between halves; half-0 stores
// overlap half-1 loads.

#define H_DIM 1024
#define W_DIM 1024
#define COLS_PER_BLOCK 16
#define CHUNKS 32
#define ROWS_PER_THREAD 16   // per half
#define HALF_ROWS 512        // CHUNKS * ROWS_PER_THREAD

__global__ __launch_bounds__(512, 3)
void cummax_kernel(const float* __restrict__ x, float* __restrict__ out) {
    const int tid   = threadIdx.x;
    const int c     = tid & (COLS_PER_BLOCK - 1);   // 0..15
    const int chunk = tid >> 4;                     // 0..31
    const int wid   = tid >> 5;                     // 0..15
    const int lane  = tid & 31;

    const int col = blockIdx.x * COLS_PER_BLOCK + c;  // 1024 % 16 == 0: no b straddle
    const int b   = col >> 10;
    const int w   = col & (W_DIM - 1);

    const int base0 = b * (H_DIM * W_DIM) + w + chunk * ROWS_PER_THREAD * W_DIM;

    __shared__ float s[2][CHUNKS][COLS_PER_BLOCK + 1];   // double buffer, padded

    float carry = -CUDART_INF_F;

#pragma unroll
    for (int half = 0; half < 2; half++) {
        const int base = base0 + half * HALF_ROWS * W_DIM;
        const float* __restrict__ src = x   + base;
        float*       __restrict__ dst = out + base;

        // Load 16 rows (coalesced: warp covers 2 rows x 64B fully-used segments).
        float v[ROWS_PER_THREAD];
#pragma unroll
        for (int i = 0; i < ROWS_PER_THREAD; i++) {
            v[i] = src[i * W_DIM];
        }
#pragma unroll
        for (int i = 1; i < ROWS_PER_THREAD; i++) {
            v[i] = fmaxf(v[i], v[i - 1]);
        }

        // Cross-chunk inclusive max-scan of totals via warp shuffles.
        s[half][chunk][c] = v[ROWS_PER_THREAD - 1];
        __syncthreads();

        // Warp `wid` scans column `wid`: lane = chunk index. 16 warps, 16 columns.
        {
            float t = s[half][lane][wid];
#pragma unroll
            for (int d = 1; d < 32; d <<= 1) {
                float o = __shfl_up_sync(0xFFFFFFFFu, t, d);
                if (lane >= d) t = fmaxf(t, o);
            }
            s[half][lane][wid] = t;
        }
        __syncthreads();

        // Exclusive carry (preceding chunks of this half + previous halves).
        const float excl = (chunk > 0) ? s[half][chunk - 1][c] : -CUDART_INF_F;
        const float m = fmaxf(carry, excl);

#pragma unroll
        for (int i = 0; i < ROWS_PER_THREAD; i++) {
            dst[i * W_DIM] = fmaxf(v[i], m);
        }

        carry = fmaxf(carry, s[half][CHUNKS - 1][c]);
    }
}

extern "C" void kernel_launch(void* const* d_in, const int* in_sizes, int n_in,
                              void* d_out, int out_size) {
    const float* x = (const float*)d_in[0];
    float* out = (float*)d_out;

    const int total_cols = 32 * W_DIM;                        // 32768
    const int grid = total_cols / COLS_PER_BLOCK;             // 2048
    cummax_kernel<<<grid, 512>>>(x, out);
}